// round 10
// baseline (speedup 1.0000x reference)
#include <cuda_runtime.h>
#include <cuda_bf16.h>
#include <cuda_fp16.h>
#include <mma.h>
#include <cstdint>

using namespace nvcuda;

#define N_V 8192
#define N_E 4096
#define FT  512
#define WN  256   // words per HTB row  (N_V/32)
#define WE  128   // words per HB  row  (N_E/32)

// ---------------- scratch (static device globals; no allocation) ------------
__device__ uint32_t g_HB [N_V * WE];
__device__ uint32_t g_HTB[N_E * WN];
__device__ float    g_y   [N_V];
__device__ float    g_hw  [N_E];
__device__ float    g_dege[N_E];
__device__ float    g_degv[N_V];
__device__ __half   g_zh  [(size_t)N_V * FT];    // fp16 z = deg_v ⊙ (xW)
__device__ __half   g_th  [N_E * FT];            // fp16 t (scaled by 2^-8)
__device__ __nv_bfloat16 g_Ah[(size_t)N_V * FT];
__device__ __nv_bfloat16 g_Al[(size_t)N_V * FT];
__device__ __nv_bfloat16 g_Bh[FT * FT];
__device__ __nv_bfloat16 g_Bl[FT * FT];

// ------------- fused bitmask builder ----------------------------------------
__global__ void __launch_bounds__(256) k_build_bits(const float* __restrict__ H) {
    __shared__ float tile[32][257];
    int e0 = blockIdx.x * 256;
    int n0 = blockIdx.y * 32;
    int t  = threadIdx.x;
#pragma unroll 4
    for (int i = 0; i < 32; i++)
        tile[i][t] = H[(size_t)(n0 + i) * N_E + e0 + t];
    __syncthreads();
    {
        int w = t >> 5, l = t & 31;
#pragma unroll 4
        for (int j = 0; j < 32; j++) {
            int c = w * 32 + j;
            uint32_t m = __ballot_sync(0xffffffffu, tile[l][c] != 0.f);
            if (l == 0) g_HTB[(size_t)(e0 + c) * WN + blockIdx.y] = m;
        }
    }
    {
        int r = t >> 3, wi = t & 7;
        uint32_t bits = 0;
#pragma unroll
        for (int kk = 0; kk < 32; kk++) {
            int k = (wi * 4 + kk) & 31;
            if (tile[r][wi * 32 + k] != 0.f) bits |= 1u << k;
        }
        g_HB[(size_t)(n0 + r) * WE + blockIdx.x * 8 + wi] = bits;
    }
}

// ---------------- y = x @ V --------------------------------------------------
__global__ void __launch_bounds__(256) k_xv(const float* __restrict__ x,
                                            const float* __restrict__ V) {
    int n = blockIdx.x * 8 + (threadIdx.x >> 5);
    int l = threadIdx.x & 31;
    float s = 0.f;
#pragma unroll
    for (int i = 0; i < 16; i++) {
        int f = i * 32 + l;
        s += x[(size_t)n * FT + f] * V[f];
    }
#pragma unroll
    for (int o = 16; o; o >>= 1) s += __shfl_xor_sync(0xffffffffu, s, o);
    if (l == 0) g_y[n] = s;
}

// -------- hw = sigmoid(H^T (xV)), deg_e; write w output ----------------------
__global__ void __launch_bounds__(128) k_hw_dege(float* __restrict__ w_out) {
    int e = blockIdx.x * 4 + (threadIdx.x >> 5);
    int l = threadIdx.x & 31;
    float s = 0.f;
    int cnt = 0;
#pragma unroll
    for (int i = 0; i < 8; i++) {
        uint32_t w = g_HTB[(size_t)e * WN + l * 8 + i];
        cnt += __popc(w);
        int base = (l * 8 + i) * 32;
        while (w) {
            int k = __ffs(w) - 1; w &= w - 1;
            s += g_y[base + k];
        }
    }
#pragma unroll
    for (int o = 16; o; o >>= 1) {
        s   += __shfl_xor_sync(0xffffffffu, s, o);
        cnt += __shfl_xor_sync(0xffffffffu, cnt, o);
    }
    if (l == 0) {
        float hw = 1.f / (1.f + expf(-s));
        g_hw[e]   = hw;
        w_out[e]  = hw;
        g_dege[e] = (float)cnt;
    }
}

// ---------------- deg_v = H @ hw ---------------------------------------------
__global__ void __launch_bounds__(128) k_degv() {
    int n = blockIdx.x * 4 + (threadIdx.x >> 5);
    int l = threadIdx.x & 31;
    float s = 0.f;
#pragma unroll
    for (int jj = 0; jj < 4; jj++) {
        int j = l * 4 + jj;
        uint32_t w = g_HB[(size_t)n * WE + j];
        while (w) { int k = __ffs(w) - 1; w &= w - 1; s += g_hw[j * 32 + k]; }
    }
#pragma unroll
    for (int o = 16; o; o >>= 1) s += __shfl_xor_sync(0xffffffffu, s, o);
    if (l == 0) g_degv[n] = s;
}

// -------- split A = deg_v ⊙ x into bf16 hi/lo --------------------------------
__global__ void __launch_bounds__(256) k_splitA(const float* __restrict__ x) {
    int gid = blockIdx.x * blockDim.x + threadIdx.x;
    int row = gid >> 6;
    int f   = (gid & 63) * 8;
    float dv = g_degv[row];
    const float4* p = reinterpret_cast<const float4*>(x + (size_t)row * FT + f);
    float v[8];
    float4 a = p[0], b = p[1];
    v[0]=a.x; v[1]=a.y; v[2]=a.z; v[3]=a.w;
    v[4]=b.x; v[5]=b.y; v[6]=b.z; v[7]=b.w;
    __nv_bfloat16 h[8], l[8];
#pragma unroll
    for (int i = 0; i < 8; i++) {
        float s = dv * v[i];
        h[i] = __float2bfloat16(s);
        l[i] = __float2bfloat16(s - __bfloat162float(h[i]));
    }
    size_t off = (size_t)row * FT + f;
    *reinterpret_cast<uint4*>(&g_Ah[off]) = *reinterpret_cast<uint4*>(h);
    *reinterpret_cast<uint4*>(&g_Al[off]) = *reinterpret_cast<uint4*>(l);
}

// -------- split B = weight into bf16 hi/lo -----------------------------------
__global__ void __launch_bounds__(256) k_splitB(const float* __restrict__ W) {
    int gid = blockIdx.x * blockDim.x + threadIdx.x;
    int off0 = gid * 8;
    const float4* p = reinterpret_cast<const float4*>(W + off0);
    float v[8];
    float4 a = p[0], b = p[1];
    v[0]=a.x; v[1]=a.y; v[2]=a.z; v[3]=a.w;
    v[4]=b.x; v[5]=b.y; v[6]=b.z; v[7]=b.w;
    __nv_bfloat16 h[8], l[8];
#pragma unroll
    for (int i = 0; i < 8; i++) {
        h[i] = __float2bfloat16(v[i]);
        l[i] = __float2bfloat16(v[i] - __bfloat162float(h[i]));
    }
    *reinterpret_cast<uint4*>(&g_Bh[off0]) = *reinterpret_cast<uint4*>(h);
    *reinterpret_cast<uint4*>(&g_Bl[off0]) = *reinterpret_cast<uint4*>(l);
}

// ------ z = (deg_v ⊙ x) @ W via dual-bf16 wmma, fp16 epilogue ---------------
#define BM 128
#define BN 128
#define BK 32
__global__ void __launch_bounds__(256) k_gemm_wmma() {
    __shared__ __nv_bfloat16 As[BM][BK + 8];
    __shared__ __nv_bfloat16 Bs[BK][BN + 8];
    int bm = blockIdx.y * BM;
    int bn = blockIdx.x * BN;
    int tid = threadIdx.x;
    int wid = tid >> 5;
    int wy = wid >> 2;
    int wx = wid & 3;

    wmma::fragment<wmma::accumulator, 16, 16, 16, float> acc[4][2];
#pragma unroll
    for (int i = 0; i < 4; i++)
#pragma unroll
        for (int j = 0; j < 2; j++) wmma::fill_fragment(acc[i][j], 0.f);

#pragma unroll
    for (int p = 0; p < 3; p++) {
        const __nv_bfloat16* gA = (p < 2) ? g_Ah : g_Al;
        const __nv_bfloat16* gB = (p == 1) ? g_Bl : g_Bh;
        for (int k0 = 0; k0 < FT; k0 += BK) {
#pragma unroll
            for (int r = 0; r < 2; r++) {
                int id = tid + r * 256;
                int arow = id >> 2, av = id & 3;
                *reinterpret_cast<uint4*>(&As[arow][av * 8]) =
                    *reinterpret_cast<const uint4*>(&gA[(size_t)(bm + arow) * FT + k0 + av * 8]);
                int brow = id >> 4, bv = id & 15;
                *reinterpret_cast<uint4*>(&Bs[brow][bv * 8]) =
                    *reinterpret_cast<const uint4*>(&gB[(size_t)(k0 + brow) * FT + bn + bv * 8]);
            }
            __syncthreads();
#pragma unroll
            for (int kk = 0; kk < 2; kk++) {
                wmma::fragment<wmma::matrix_a, 16, 16, 16, __nv_bfloat16, wmma::row_major> af[4];
                wmma::fragment<wmma::matrix_b, 16, 16, 16, __nv_bfloat16, wmma::row_major> bf[2];
#pragma unroll
                for (int i = 0; i < 4; i++)
                    wmma::load_matrix_sync(af[i], &As[wy * 64 + i * 16][kk * 16], BK + 8);
#pragma unroll
                for (int j = 0; j < 2; j++)
                    wmma::load_matrix_sync(bf[j], &Bs[kk * 16][wx * 32 + j * 16], BN + 8);
#pragma unroll
                for (int i = 0; i < 4; i++)
#pragma unroll
                    for (int j = 0; j < 2; j++)
                        wmma::mma_sync(acc[i][j], af[i], bf[j], acc[i][j]);
            }
            __syncthreads();
        }
    }
    // fp16 epilogue: convert fp32 acc fragments to half in-register and store.
#pragma unroll
    for (int i = 0; i < 4; i++) {
        int row = bm + wy * 64 + i * 16;
#pragma unroll
        for (int j = 0; j < 2; j++) {
            int col = bn + wx * 32 + j * 16;
            wmma::fragment<wmma::accumulator, 16, 16, 16, __half> hacc;
#pragma unroll
            for (int q = 0; q < hacc.num_elements; q++)
                hacc.x[q] = __float2half(acc[i][j].x[q]);
            wmma::store_matrix_sync(&g_zh[(size_t)row * FT + col], hacc,
                                    FT, wmma::mem_row_major);
        }
    }
}

__device__ __forceinline__ void add_h4(float4& acc, uint2 v) {
    float2 p = __half22float2(*reinterpret_cast<__half2*>(&v.x));
    float2 q = __half22float2(*reinterpret_cast<__half2*>(&v.y));
    acc.x += p.x; acc.y += p.y; acc.z += q.x; acc.w += q.y;
}

// ------------ t = (w*deg_e/256) ⊙ H^T @ z  (fp16 gather) --------------------
#define CAP_E 512
__global__ void __launch_bounds__(128) k_edge_gather_t() {
    int e = blockIdx.x;
    int tid = threadIdx.x;
    __shared__ int idx[CAP_E];
    __shared__ int cnt;
    if (tid == 0) cnt = 0;
    __syncthreads();
    for (int j = tid; j < WN; j += 128) {
        uint32_t w = g_HTB[(size_t)e * WN + j];
        if (w) {
            int pos = atomicAdd(&cnt, __popc(w));
            while (w) {
                int k = __ffs(w) - 1; w &= w - 1;
                if (pos < CAP_E) idx[pos] = j * 32 + k;
                pos++;
            }
        }
    }
    __syncthreads();
    int m = cnt < CAP_E ? cnt : CAP_E;

    float4 accA = {0.f, 0.f, 0.f, 0.f};
    float4 accB = {0.f, 0.f, 0.f, 0.f};
    const uint2* z2 = reinterpret_cast<const uint2*>(g_zh);
    int i = 0;
    for (; i + 8 <= m; i += 8) {
        uint2 v0 = z2[(size_t)idx[i]     * 128 + tid];
        uint2 v1 = z2[(size_t)idx[i + 1] * 128 + tid];
        uint2 v2 = z2[(size_t)idx[i + 2] * 128 + tid];
        uint2 v3 = z2[(size_t)idx[i + 3] * 128 + tid];
        uint2 v4 = z2[(size_t)idx[i + 4] * 128 + tid];
        uint2 v5 = z2[(size_t)idx[i + 5] * 128 + tid];
        uint2 v6 = z2[(size_t)idx[i + 6] * 128 + tid];
        uint2 v7 = z2[(size_t)idx[i + 7] * 128 + tid];
        add_h4(accA, v0); add_h4(accB, v1);
        add_h4(accA, v2); add_h4(accB, v3);
        add_h4(accA, v4); add_h4(accB, v5);
        add_h4(accA, v6); add_h4(accB, v7);
    }
    for (; i < m; i++) add_h4(accA, z2[(size_t)idx[i] * 128 + tid]);
    accA.x += accB.x; accA.y += accB.y; accA.z += accB.z; accA.w += accB.w;

    float s = g_hw[e] * g_dege[e] * (1.f / 256.f);   // 2^-8 scale for fp16 range
    __half2 r[2];
    r[0] = __floats2half2_rn(s * accA.x, s * accA.y);
    r[1] = __floats2half2_rn(s * accA.z, s * accA.w);
    reinterpret_cast<uint2*>(g_th)[(size_t)e * 128 + tid] = *reinterpret_cast<uint2*>(r);
}

// ------------ out = deg_v*256 ⊙ (H @ t) + bias  (fp16 gather) ---------------
#define CAP_V 320
__global__ void __launch_bounds__(128) k_vertex_gather(const float* __restrict__ bias,
                                                       float* __restrict__ out) {
    int n = blockIdx.x;
    int tid = threadIdx.x;
    __shared__ int idx[CAP_V];
    __shared__ int cnt;
    if (tid == 0) cnt = 0;
    __syncthreads();
    if (tid < WE) {
        uint32_t w = g_HB[(size_t)n * WE + tid];
        if (w) {
            int pos = atomicAdd(&cnt, __popc(w));
            while (w) {
                int k = __ffs(w) - 1; w &= w - 1;
                if (pos < CAP_V) idx[pos] = tid * 32 + k;
                pos++;
            }
        }
    }
    __syncthreads();
    int m = cnt < CAP_V ? cnt : CAP_V;

    float4 accA = {0.f, 0.f, 0.f, 0.f};
    float4 accB = {0.f, 0.f, 0.f, 0.f};
    const uint2* t2 = reinterpret_cast<const uint2*>(g_th);
    int i = 0;
    for (; i + 8 <= m; i += 8) {
        uint2 v0 = t2[(size_t)idx[i]     * 128 + tid];
        uint2 v1 = t2[(size_t)idx[i + 1] * 128 + tid];
        uint2 v2 = t2[(size_t)idx[i + 2] * 128 + tid];
        uint2 v3 = t2[(size_t)idx[i + 3] * 128 + tid];
        uint2 v4 = t2[(size_t)idx[i + 4] * 128 + tid];
        uint2 v5 = t2[(size_t)idx[i + 5] * 128 + tid];
        uint2 v6 = t2[(size_t)idx[i + 6] * 128 + tid];
        uint2 v7 = t2[(size_t)idx[i + 7] * 128 + tid];
        add_h4(accA, v0); add_h4(accB, v1);
        add_h4(accA, v2); add_h4(accB, v3);
        add_h4(accA, v4); add_h4(accB, v5);
        add_h4(accA, v6); add_h4(accB, v7);
    }
    for (; i < m; i++) add_h4(accA, t2[(size_t)idx[i] * 128 + tid]);
    accA.x += accB.x; accA.y += accB.y; accA.z += accB.z; accA.w += accB.w;

    float dv = g_degv[n] * 256.f;                    // undo 2^-8 scale
    float4 b = reinterpret_cast<const float4*>(bias)[tid];
    float4 r = {dv * accA.x + b.x, dv * accA.y + b.y,
                dv * accA.z + b.z, dv * accA.w + b.w};
    reinterpret_cast<float4*>(out)[(size_t)n * 128 + tid] = r;
}

// ---------------- launch -----------------------------------------------------
extern "C" void kernel_launch(void* const* d_in, const int* in_sizes, int n_in,
                              void* d_out, int out_size) {
    const float* x      = (const float*)d_in[0];
    const float* H      = (const float*)d_in[1];
    const float* weight = (const float*)d_in[2];
    const float* V      = (const float*)d_in[3];
    const float* bias   = (const float*)d_in[4];
    float* out   = (float*)d_out;
    float* w_out = (float*)d_out + (size_t)N_V * FT;

    k_build_bits<<<dim3(N_E / 256, N_V / 32), 256>>>(H);
    k_xv        <<<N_V / 8, 256>>>(x, V);
    k_splitB    <<<(FT * FT / 8) / 256, 256>>>(weight);
    k_hw_dege   <<<N_E / 4, 128>>>(w_out);
    k_degv      <<<N_V / 4, 128>>>();
    k_splitA    <<<(N_V * 64) / 256, 256>>>(x);
    k_gemm_wmma <<<dim3(FT / BN, N_V / BM), 256>>>();
    k_edge_gather_t<<<N_E, 128>>>();
    k_vertex_gather<<<N_V, 128>>>(bias, out);
}

// round 12
// speedup vs baseline: 1.1190x; 1.1190x over previous
#include <cuda_runtime.h>
#include <cuda_bf16.h>
#include <cuda_fp16.h>
#include <mma.h>
#include <cstdint>

using namespace nvcuda;

#define N_V 8192
#define N_E 4096
#define FT  512
#define WN  256   // words per HTB row  (N_V/32)
#define WE  128   // words per HB  row  (N_E/32)

// ---------------- scratch (static device globals; no allocation) ------------
__device__ uint32_t g_HB [N_V * WE];
__device__ uint32_t g_HTB[N_E * WN];
__device__ float    g_y   [N_V];
__device__ float    g_hw  [N_E];
__device__ float    g_dege[N_E];
__device__ float    g_degv[N_V];
__device__ __half   g_zh  [(size_t)N_V * FT];    // fp16 out0 = xW (UNscaled)
__device__ __half   g_th  [N_E * FT];            // fp16 t (scaled by 2^-8)
__device__ __nv_bfloat16 g_Ah[(size_t)N_V * FT];
__device__ __nv_bfloat16 g_Al[(size_t)N_V * FT];
__device__ __nv_bfloat16 g_Bh[FT * FT];
__device__ __nv_bfloat16 g_Bl[FT * FT];

// ------------- fused bitmask builder ----------------------------------------
__global__ void __launch_bounds__(256) k_build_bits(const float* __restrict__ H) {
    __shared__ float tile[32][257];
    int e0 = blockIdx.x * 256;
    int n0 = blockIdx.y * 32;
    int t  = threadIdx.x;
#pragma unroll 4
    for (int i = 0; i < 32; i++)
        tile[i][t] = H[(size_t)(n0 + i) * N_E + e0 + t];
    __syncthreads();
    {
        int w = t >> 5, l = t & 31;
#pragma unroll 4
        for (int j = 0; j < 32; j++) {
            int c = w * 32 + j;
            uint32_t m = __ballot_sync(0xffffffffu, tile[l][c] != 0.f);
            if (l == 0) g_HTB[(size_t)(e0 + c) * WN + blockIdx.y] = m;
        }
    }
    {
        int r = t >> 3, wi = t & 7;
        uint32_t bits = 0;
#pragma unroll
        for (int kk = 0; kk < 32; kk++) {
            int k = (wi * 4 + kk) & 31;
            if (tile[r][wi * 32 + k] != 0.f) bits |= 1u << k;
        }
        g_HB[(size_t)(n0 + r) * WE + blockIdx.x * 8 + wi] = bits;
    }
}

// ---------------- y = x @ V --------------------------------------------------
__global__ void __launch_bounds__(256) k_xv(const float* __restrict__ x,
                                            const float* __restrict__ V) {
    int n = blockIdx.x * 8 + (threadIdx.x >> 5);
    int l = threadIdx.x & 31;
    float s = 0.f;
#pragma unroll
    for (int i = 0; i < 16; i++) {
        int f = i * 32 + l;
        s += x[(size_t)n * FT + f] * V[f];
    }
#pragma unroll
    for (int o = 16; o; o >>= 1) s += __shfl_xor_sync(0xffffffffu, s, o);
    if (l == 0) g_y[n] = s;
}

// -------- hw = sigmoid(H^T (xV)), deg_e; write w output ----------------------
__global__ void __launch_bounds__(128) k_hw_dege(float* __restrict__ w_out) {
    int e = blockIdx.x * 4 + (threadIdx.x >> 5);
    int l = threadIdx.x & 31;
    float s = 0.f;
    int cnt = 0;
#pragma unroll
    for (int i = 0; i < 8; i++) {
        uint32_t w = g_HTB[(size_t)e * WN + l * 8 + i];
        cnt += __popc(w);
        int base = (l * 8 + i) * 32;
        while (w) {
            int k = __ffs(w) - 1; w &= w - 1;
            s += g_y[base + k];
        }
    }
#pragma unroll
    for (int o = 16; o; o >>= 1) {
        s   += __shfl_xor_sync(0xffffffffu, s, o);
        cnt += __shfl_xor_sync(0xffffffffu, cnt, o);
    }
    if (l == 0) {
        float hw = 1.f / (1.f + expf(-s));
        g_hw[e]   = hw;
        w_out[e]  = hw;
        g_dege[e] = (float)cnt;
    }
}

// ---------------- deg_v = H @ hw ---------------------------------------------
__global__ void __launch_bounds__(128) k_degv() {
    int n = blockIdx.x * 4 + (threadIdx.x >> 5);
    int l = threadIdx.x & 31;
    float s = 0.f;
#pragma unroll
    for (int jj = 0; jj < 4; jj++) {
        int j = l * 4 + jj;
        uint32_t w = g_HB[(size_t)n * WE + j];
        while (w) { int k = __ffs(w) - 1; w &= w - 1; s += g_hw[j * 32 + k]; }
    }
#pragma unroll
    for (int o = 16; o; o >>= 1) s += __shfl_xor_sync(0xffffffffu, s, o);
    if (l == 0) g_degv[n] = s;
}

// -------- split A = x into bf16 hi/lo (NO degv scale) ------------------------
__global__ void __launch_bounds__(256) k_splitA(const float* __restrict__ x) {
    int gid = blockIdx.x * blockDim.x + threadIdx.x;
    size_t off = (size_t)gid * 8;
    const float4* p = reinterpret_cast<const float4*>(x + off);
    float v[8];
    float4 a = p[0], b = p[1];
    v[0]=a.x; v[1]=a.y; v[2]=a.z; v[3]=a.w;
    v[4]=b.x; v[5]=b.y; v[6]=b.z; v[7]=b.w;
    __nv_bfloat16 h[8], l[8];
#pragma unroll
    for (int i = 0; i < 8; i++) {
        h[i] = __float2bfloat16(v[i]);
        l[i] = __float2bfloat16(v[i] - __bfloat162float(h[i]));
    }
    *reinterpret_cast<uint4*>(&g_Ah[off]) = *reinterpret_cast<uint4*>(h);
    *reinterpret_cast<uint4*>(&g_Al[off]) = *reinterpret_cast<uint4*>(l);
}

// -------- split B = weight into bf16 hi/lo -----------------------------------
__global__ void __launch_bounds__(256) k_splitB(const float* __restrict__ W) {
    int gid = blockIdx.x * blockDim.x + threadIdx.x;
    size_t off = (size_t)gid * 8;
    const float4* p = reinterpret_cast<const float4*>(W + off);
    float v[8];
    float4 a = p[0], b = p[1];
    v[0]=a.x; v[1]=a.y; v[2]=a.z; v[3]=a.w;
    v[4]=b.x; v[5]=b.y; v[6]=b.z; v[7]=b.w;
    __nv_bfloat16 h[8], l[8];
#pragma unroll
    for (int i = 0; i < 8; i++) {
        h[i] = __float2bfloat16(v[i]);
        l[i] = __float2bfloat16(v[i] - __bfloat162float(h[i]));
    }
    *reinterpret_cast<uint4*>(&g_Bh[off]) = *reinterpret_cast<uint4*>(h);
    *reinterpret_cast<uint4*>(&g_Bl[off]) = *reinterpret_cast<uint4*>(l);
}

// ------ out0 = x @ W via dual-bf16 wmma, fused 3 products, fp16 epilogue -----
#define BM 128
#define BN 128
#define BK 32
__global__ void __launch_bounds__(256) k_gemm_wmma() {
    __shared__ __nv_bfloat16 Ash[BM][BK + 8];
    __shared__ __nv_bfloat16 Asl[BM][BK + 8];
    __shared__ __nv_bfloat16 Bsh[BK][BN + 8];
    __shared__ __nv_bfloat16 Bsl[BK][BN + 8];
    int bm = blockIdx.y * BM;
    int bn = blockIdx.x * BN;
    int tid = threadIdx.x;
    int wid = tid >> 5;
    int wy = wid >> 2;
    int wx = wid & 3;

    wmma::fragment<wmma::accumulator, 16, 16, 16, float> acc[4][2];
#pragma unroll
    for (int i = 0; i < 4; i++)
#pragma unroll
        for (int j = 0; j < 2; j++) wmma::fill_fragment(acc[i][j], 0.f);

    for (int k0 = 0; k0 < FT; k0 += BK) {
#pragma unroll
        for (int r = 0; r < 2; r++) {
            int id = tid + r * 256;
            int arow = id >> 2, av = id & 3;
            size_t aoff = (size_t)(bm + arow) * FT + k0 + av * 8;
            *reinterpret_cast<uint4*>(&Ash[arow][av * 8]) =
                *reinterpret_cast<const uint4*>(&g_Ah[aoff]);
            *reinterpret_cast<uint4*>(&Asl[arow][av * 8]) =
                *reinterpret_cast<const uint4*>(&g_Al[aoff]);
            int brow = id >> 4, bv = id & 15;
            size_t boff = (size_t)(k0 + brow) * FT + bn + bv * 8;
            *reinterpret_cast<uint4*>(&Bsh[brow][bv * 8]) =
                *reinterpret_cast<const uint4*>(&g_Bh[boff]);
            *reinterpret_cast<uint4*>(&Bsl[brow][bv * 8]) =
                *reinterpret_cast<const uint4*>(&g_Bl[boff]);
        }
        __syncthreads();
#pragma unroll
        for (int kk = 0; kk < 2; kk++) {
            wmma::fragment<wmma::matrix_a, 16, 16, 16, __nv_bfloat16, wmma::row_major> afh[4], afl[4];
            wmma::fragment<wmma::matrix_b, 16, 16, 16, __nv_bfloat16, wmma::row_major> bfh[2], bfl[2];
#pragma unroll
            for (int i = 0; i < 4; i++) {
                wmma::load_matrix_sync(afh[i], &Ash[wy * 64 + i * 16][kk * 16], BK + 8);
                wmma::load_matrix_sync(afl[i], &Asl[wy * 64 + i * 16][kk * 16], BK + 8);
            }
#pragma unroll
            for (int j = 0; j < 2; j++) {
                wmma::load_matrix_sync(bfh[j], &Bsh[kk * 16][wx * 32 + j * 16], BN + 8);
                wmma::load_matrix_sync(bfl[j], &Bsl[kk * 16][wx * 32 + j * 16], BN + 8);
            }
#pragma unroll
            for (int i = 0; i < 4; i++)
#pragma unroll
                for (int j = 0; j < 2; j++) {
                    wmma::mma_sync(acc[i][j], afh[i], bfh[j], acc[i][j]);
                    wmma::mma_sync(acc[i][j], afh[i], bfl[j], acc[i][j]);
                    wmma::mma_sync(acc[i][j], afl[i], bfh[j], acc[i][j]);
                }
        }
        __syncthreads();
    }
#pragma unroll
    for (int i = 0; i < 4; i++) {
        int row = bm + wy * 64 + i * 16;
#pragma unroll
        for (int j = 0; j < 2; j++) {
            int col = bn + wx * 32 + j * 16;
            wmma::fragment<wmma::accumulator, 16, 16, 16, __half> hacc;
#pragma unroll
            for (int q = 0; q < hacc.num_elements; q++)
                hacc.x[q] = __float2half(acc[i][j].x[q]);
            wmma::store_matrix_sync(&g_zh[(size_t)row * FT + col], hacc,
                                    FT, wmma::mem_row_major);
        }
    }
}

__device__ __forceinline__ void fma_h4(float4& acc, float dv, uint2 v) {
    float2 p = __half22float2(*reinterpret_cast<__half2*>(&v.x));
    float2 q = __half22float2(*reinterpret_cast<__half2*>(&v.y));
    acc.x += dv * p.x; acc.y += dv * p.y; acc.z += dv * q.x; acc.w += dv * q.y;
}
__device__ __forceinline__ void add_h4(float4& acc, uint2 v) {
    float2 p = __half22float2(*reinterpret_cast<__half2*>(&v.x));
    float2 q = __half22float2(*reinterpret_cast<__half2*>(&v.y));
    acc.x += p.x; acc.y += p.y; acc.z += q.x; acc.w += q.y;
}

// ------ t = (w*deg_e/256) ⊙ H^T @ (deg_v ⊙ out0)  (fp16 gather + dv table) ---
#define CAP_E 512
__global__ void __launch_bounds__(128) k_edge_gather_t() {
    int e = blockIdx.x;
    int tid = threadIdx.x;
    __shared__ int   idx[CAP_E];
    __shared__ float dvs[CAP_E];
    __shared__ int   cnt;
    if (tid == 0) cnt = 0;
    __syncthreads();
    for (int j = tid; j < WN; j += 128) {
        uint32_t w = g_HTB[(size_t)e * WN + j];
        if (w) {
            int pos = atomicAdd(&cnt, __popc(w));
            while (w) {
                int k = __ffs(w) - 1; w &= w - 1;
                if (pos < CAP_E) idx[pos] = j * 32 + k;
                pos++;
            }
        }
    }
    __syncthreads();
    int m = cnt < CAP_E ? cnt : CAP_E;
    for (int i = tid; i < m; i += 128) dvs[i] = g_degv[idx[i]];
    __syncthreads();

    float4 accA = {0.f, 0.f, 0.f, 0.f};
    float4 accB = {0.f, 0.f, 0.f, 0.f};
    const uint2* z2 = reinterpret_cast<const uint2*>(g_zh);
    int i = 0;
    for (; i + 4 <= m; i += 4) {
        uint2 v0 = z2[(size_t)idx[i]     * 128 + tid];
        uint2 v1 = z2[(size_t)idx[i + 1] * 128 + tid];
        uint2 v2 = z2[(size_t)idx[i + 2] * 128 + tid];
        uint2 v3 = z2[(size_t)idx[i + 3] * 128 + tid];
        fma_h4(accA, dvs[i],     v0);
        fma_h4(accB, dvs[i + 1], v1);
        fma_h4(accA, dvs[i + 2], v2);
        fma_h4(accB, dvs[i + 3], v3);
    }
    for (; i < m; i++) fma_h4(accA, dvs[i], z2[(size_t)idx[i] * 128 + tid]);
    accA.x += accB.x; accA.y += accB.y; accA.z += accB.z; accA.w += accB.w;

    float s = g_hw[e] * g_dege[e] * (1.f / 256.f);   // 2^-8 scale for fp16 range
    __half2 r[2];
    r[0] = __floats2half2_rn(s * accA.x, s * accA.y);
    r[1] = __floats2half2_rn(s * accA.z, s * accA.w);
    reinterpret_cast<uint2*>(g_th)[(size_t)e * 128 + tid] = *reinterpret_cast<uint2*>(r);
}

// ------------ out = deg_v*256 ⊙ (H @ t) + bias  (fp16 gather) ---------------
#define CAP_V 320
__global__ void __launch_bounds__(128) k_vertex_gather(const float* __restrict__ bias,
                                                       float* __restrict__ out) {
    int n = blockIdx.x;
    int tid = threadIdx.x;
    __shared__ int idx[CAP_V];
    __shared__ int cnt;
    if (tid == 0) cnt = 0;
    __syncthreads();
    if (tid < WE) {
        uint32_t w = g_HB[(size_t)n * WE + tid];
        if (w) {
            int pos = atomicAdd(&cnt, __popc(w));
            while (w) {
                int k = __ffs(w) - 1; w &= w - 1;
                if (pos < CAP_V) idx[pos] = tid * 32 + k;
                pos++;
            }
        }
    }
    __syncthreads();
    int m = cnt < CAP_V ? cnt : CAP_V;

    float4 accA = {0.f, 0.f, 0.f, 0.f};
    float4 accB = {0.f, 0.f, 0.f, 0.f};
    const uint2* t2 = reinterpret_cast<const uint2*>(g_th);
    int i = 0;
    for (; i + 4 <= m; i += 4) {
        uint2 v0 = t2[(size_t)idx[i]     * 128 + tid];
        uint2 v1 = t2[(size_t)idx[i + 1] * 128 + tid];
        uint2 v2 = t2[(size_t)idx[i + 2] * 128 + tid];
        uint2 v3 = t2[(size_t)idx[i + 3] * 128 + tid];
        add_h4(accA, v0); add_h4(accB, v1);
        add_h4(accA, v2); add_h4(accB, v3);
    }
    for (; i < m; i++) add_h4(accA, t2[(size_t)idx[i] * 128 + tid]);
    accA.x += accB.x; accA.y += accB.y; accA.z += accB.z; accA.w += accB.w;

    float dv = g_degv[n] * 256.f;                    // undo 2^-8 scale
    float4 b = reinterpret_cast<const float4*>(bias)[tid];
    float4 r = {dv * accA.x + b.x, dv * accA.y + b.y,
                dv * accA.z + b.z, dv * accA.w + b.w};
    reinterpret_cast<float4*>(out)[(size_t)n * 128 + tid] = r;
}

// ---------------- launch -----------------------------------------------------
extern "C" void kernel_launch(void* const* d_in, const int* in_sizes, int n_in,
                              void* d_out, int out_size) {
    const float* x      = (const float*)d_in[0];
    const float* H      = (const float*)d_in[1];
    const float* weight = (const float*)d_in[2];
    const float* V      = (const float*)d_in[3];
    const float* bias   = (const float*)d_in[4];
    float* out   = (float*)d_out;
    float* w_out = (float*)d_out + (size_t)N_V * FT;

    // One-time stream/event setup (first call = uncaptured correctness run).
    static cudaStream_t s2 = nullptr;
    static cudaEvent_t  evF = nullptr, evJ = nullptr;
    if (s2 == nullptr) {
        cudaStreamCreateWithFlags(&s2, cudaStreamNonBlocking);
        cudaEventCreateWithFlags(&evF, cudaEventDisableTiming);
        cudaEventCreateWithFlags(&evJ, cudaEventDisableTiming);
    }

    // Fork: GEMM chain (independent of bitmask chain) on side stream s2.
    cudaEventRecord(evF, 0);
    cudaStreamWaitEvent(s2, evF, 0);
    k_splitA   <<<((size_t)N_V * FT / 8) / 256, 256, 0, s2>>>(x);
    k_splitB   <<<(FT * FT / 8) / 256, 256, 0, s2>>>(weight);
    k_gemm_wmma<<<dim3(FT / BN, N_V / BM), 256, 0, s2>>>();
    cudaEventRecord(evJ, s2);

    // Main stream: bitmask + edge-weight chain.
    k_build_bits<<<dim3(N_E / 256, N_V / 32), 256>>>(H);
    k_xv        <<<N_V / 8, 256>>>(x, V);
    k_hw_dege   <<<N_E / 4, 128>>>(w_out);
    k_degv      <<<N_V / 4, 128>>>();

    // Join, then the two dependent gathers.
    cudaStreamWaitEvent(0, evJ, 0);
    k_edge_gather_t<<<N_E, 128>>>();
    k_vertex_gather<<<N_V, 128>>>(bias, out);
}

// round 13
// speedup vs baseline: 1.2254x; 1.0951x over previous
#include <cuda_runtime.h>
#include <cuda_bf16.h>
#include <cuda_fp16.h>
#include <mma.h>
#include <cstdint>

using namespace nvcuda;

#define N_V 8192
#define N_E 4096
#define FT  512
#define WN  256   // words per HTB row  (N_V/32)
#define WE  128   // words per HB  row  (N_E/32)

// ---------------- scratch (static device globals; no allocation) ------------
__device__ uint32_t g_HB [N_V * WE];
__device__ uint32_t g_HTB[N_E * WN];
__device__ float    g_y   [N_V];
__device__ float    g_hw  [N_E];
__device__ float    g_dege[N_E];
__device__ float    g_degv[N_V];
__device__ __half   g_zh  [(size_t)N_V * FT];    // fp16 out0 = xW (unscaled)
__device__ __half   g_th  [N_E * FT];            // fp16 t (scaled by 2^-8)
__device__ __nv_bfloat16 g_Ah[(size_t)N_V * FT];
__device__ __nv_bfloat16 g_Al[(size_t)N_V * FT];
__device__ __nv_bfloat16 g_Bh[FT * FT];
__device__ __nv_bfloat16 g_Bl[FT * FT];

// ------------- fused bitmask builder ----------------------------------------
__global__ void __launch_bounds__(256) k_build_bits(const float* __restrict__ H) {
    __shared__ float tile[32][257];
    int e0 = blockIdx.x * 256;
    int n0 = blockIdx.y * 32;
    int t  = threadIdx.x;
#pragma unroll 4
    for (int i = 0; i < 32; i++)
        tile[i][t] = H[(size_t)(n0 + i) * N_E + e0 + t];
    __syncthreads();
    {
        int w = t >> 5, l = t & 31;
#pragma unroll 4
        for (int j = 0; j < 32; j++) {
            int c = w * 32 + j;
            uint32_t m = __ballot_sync(0xffffffffu, tile[l][c] != 0.f);
            if (l == 0) g_HTB[(size_t)(e0 + c) * WN + blockIdx.y] = m;
        }
    }
    {
        int r = t >> 3, wi = t & 7;
        uint32_t bits = 0;
#pragma unroll
        for (int kk = 0; kk < 32; kk++) {
            int k = (wi * 4 + kk) & 31;
            if (tile[r][wi * 32 + k] != 0.f) bits |= 1u << k;
        }
        g_HB[(size_t)(n0 + r) * WE + blockIdx.x * 8 + wi] = bits;
    }
}

// ---------------- y = x @ V --------------------------------------------------
__global__ void __launch_bounds__(256) k_xv(const float* __restrict__ x,
                                            const float* __restrict__ V) {
    int n = blockIdx.x * 8 + (threadIdx.x >> 5);
    int l = threadIdx.x & 31;
    float s = 0.f;
#pragma unroll
    for (int i = 0; i < 16; i++) {
        int f = i * 32 + l;
        s += x[(size_t)n * FT + f] * V[f];
    }
#pragma unroll
    for (int o = 16; o; o >>= 1) s += __shfl_xor_sync(0xffffffffu, s, o);
    if (l == 0) g_y[n] = s;
}

// -------- hw = sigmoid(H^T (xV)), deg_e; write w output ----------------------
__global__ void __launch_bounds__(128) k_hw_dege(float* __restrict__ w_out) {
    int e = blockIdx.x * 4 + (threadIdx.x >> 5);
    int l = threadIdx.x & 31;
    float s = 0.f;
    int cnt = 0;
#pragma unroll
    for (int i = 0; i < 8; i++) {
        uint32_t w = g_HTB[(size_t)e * WN + l * 8 + i];
        cnt += __popc(w);
        int base = (l * 8 + i) * 32;
        while (w) {
            int k = __ffs(w) - 1; w &= w - 1;
            s += g_y[base + k];
        }
    }
#pragma unroll
    for (int o = 16; o; o >>= 1) {
        s   += __shfl_xor_sync(0xffffffffu, s, o);
        cnt += __shfl_xor_sync(0xffffffffu, cnt, o);
    }
    if (l == 0) {
        float hw = 1.f / (1.f + expf(-s));
        g_hw[e]   = hw;
        w_out[e]  = hw;
        g_dege[e] = (float)cnt;
    }
}

// ---------------- deg_v = H @ hw ---------------------------------------------
__global__ void __launch_bounds__(128) k_degv() {
    int n = blockIdx.x * 4 + (threadIdx.x >> 5);
    int l = threadIdx.x & 31;
    float s = 0.f;
#pragma unroll
    for (int jj = 0; jj < 4; jj++) {
        int j = l * 4 + jj;
        uint32_t w = g_HB[(size_t)n * WE + j];
        while (w) { int k = __ffs(w) - 1; w &= w - 1; s += g_hw[j * 32 + k]; }
    }
#pragma unroll
    for (int o = 16; o; o >>= 1) s += __shfl_xor_sync(0xffffffffu, s, o);
    if (l == 0) g_degv[n] = s;
}

// -------- split A = x into bf16 hi/lo ----------------------------------------
__global__ void __launch_bounds__(256) k_splitA(const float* __restrict__ x) {
    int gid = blockIdx.x * blockDim.x + threadIdx.x;
    size_t off = (size_t)gid * 8;
    const float4* p = reinterpret_cast<const float4*>(x + off);
    float v[8];
    float4 a = p[0], b = p[1];
    v[0]=a.x; v[1]=a.y; v[2]=a.z; v[3]=a.w;
    v[4]=b.x; v[5]=b.y; v[6]=b.z; v[7]=b.w;
    __nv_bfloat16 h[8], l[8];
#pragma unroll
    for (int i = 0; i < 8; i++) {
        h[i] = __float2bfloat16(v[i]);
        l[i] = __float2bfloat16(v[i] - __bfloat162float(h[i]));
    }
    *reinterpret_cast<uint4*>(&g_Ah[off]) = *reinterpret_cast<uint4*>(h);
    *reinterpret_cast<uint4*>(&g_Al[off]) = *reinterpret_cast<uint4*>(l);
}

// -------- split B = weight into bf16 hi/lo -----------------------------------
__global__ void __launch_bounds__(256) k_splitB(const float* __restrict__ W) {
    int gid = blockIdx.x * blockDim.x + threadIdx.x;
    size_t off = (size_t)gid * 8;
    const float4* p = reinterpret_cast<const float4*>(W + off);
    float v[8];
    float4 a = p[0], b = p[1];
    v[0]=a.x; v[1]=a.y; v[2]=a.z; v[3]=a.w;
    v[4]=b.x; v[5]=b.y; v[6]=b.z; v[7]=b.w;
    __nv_bfloat16 h[8], l[8];
#pragma unroll
    for (int i = 0; i < 8; i++) {
        h[i] = __float2bfloat16(v[i]);
        l[i] = __float2bfloat16(v[i] - __bfloat162float(h[i]));
    }
    *reinterpret_cast<uint4*>(&g_Bh[off]) = *reinterpret_cast<uint4*>(h);
    *reinterpret_cast<uint4*>(&g_Bl[off]) = *reinterpret_cast<uint4*>(l);
}

// ------ out0 = x @ W via dual-bf16 wmma, fused 3 products, fp16 epilogue -----
#define BM 128
#define BN 128
#define BK 32
__global__ void __launch_bounds__(256) k_gemm_wmma() {
    __shared__ __nv_bfloat16 Ash[BM][BK + 8];
    __shared__ __nv_bfloat16 Asl[BM][BK + 8];
    __shared__ __nv_bfloat16 Bsh[BK][BN + 8];
    __shared__ __nv_bfloat16 Bsl[BK][BN + 8];
    int bm = blockIdx.y * BM;
    int bn = blockIdx.x * BN;
    int tid = threadIdx.x;
    int wid = tid >> 5;
    int wy = wid >> 2;
    int wx = wid & 3;

    wmma::fragment<wmma::accumulator, 16, 16, 16, float> acc[4][2];
#pragma unroll
    for (int i = 0; i < 4; i++)
#pragma unroll
        for (int j = 0; j < 2; j++) wmma::fill_fragment(acc[i][j], 0.f);

    for (int k0 = 0; k0 < FT; k0 += BK) {
#pragma unroll
        for (int r = 0; r < 2; r++) {
            int id = tid + r * 256;
            int arow = id >> 2, av = id & 3;
            size_t aoff = (size_t)(bm + arow) * FT + k0 + av * 8;
            *reinterpret_cast<uint4*>(&Ash[arow][av * 8]) =
                *reinterpret_cast<const uint4*>(&g_Ah[aoff]);
            *reinterpret_cast<uint4*>(&Asl[arow][av * 8]) =
                *reinterpret_cast<const uint4*>(&g_Al[aoff]);
            int brow = id >> 4, bv = id & 15;
            size_t boff = (size_t)(k0 + brow) * FT + bn + bv * 8;
            *reinterpret_cast<uint4*>(&Bsh[brow][bv * 8]) =
                *reinterpret_cast<const uint4*>(&g_Bh[boff]);
            *reinterpret_cast<uint4*>(&Bsl[brow][bv * 8]) =
                *reinterpret_cast<const uint4*>(&g_Bl[boff]);
        }
        __syncthreads();
#pragma unroll
        for (int kk = 0; kk < 2; kk++) {
            wmma::fragment<wmma::matrix_a, 16, 16, 16, __nv_bfloat16, wmma::row_major> afh[4], afl[4];
            wmma::fragment<wmma::matrix_b, 16, 16, 16, __nv_bfloat16, wmma::row_major> bfh[2], bfl[2];
#pragma unroll
            for (int i = 0; i < 4; i++) {
                wmma::load_matrix_sync(afh[i], &Ash[wy * 64 + i * 16][kk * 16], BK + 8);
                wmma::load_matrix_sync(afl[i], &Asl[wy * 64 + i * 16][kk * 16], BK + 8);
            }
#pragma unroll
            for (int j = 0; j < 2; j++) {
                wmma::load_matrix_sync(bfh[j], &Bsh[kk * 16][wx * 32 + j * 16], BN + 8);
                wmma::load_matrix_sync(bfl[j], &Bsl[kk * 16][wx * 32 + j * 16], BN + 8);
            }
#pragma unroll
            for (int i = 0; i < 4; i++)
#pragma unroll
                for (int j = 0; j < 2; j++) {
                    wmma::mma_sync(acc[i][j], afh[i], bfh[j], acc[i][j]);
                    wmma::mma_sync(acc[i][j], afh[i], bfl[j], acc[i][j]);
                    wmma::mma_sync(acc[i][j], afl[i], bfh[j], acc[i][j]);
                }
        }
        __syncthreads();
    }
#pragma unroll
    for (int i = 0; i < 4; i++) {
        int row = bm + wy * 64 + i * 16;
#pragma unroll
        for (int j = 0; j < 2; j++) {
            int col = bn + wx * 32 + j * 16;
            wmma::fragment<wmma::accumulator, 16, 16, 16, __half> hacc;
#pragma unroll
            for (int q = 0; q < hacc.num_elements; q++)
                hacc.x[q] = __float2half(acc[i][j].x[q]);
            wmma::store_matrix_sync(&g_zh[(size_t)row * FT + col], hacc,
                                    FT, wmma::mem_row_major);
        }
    }
}

// 8 halves (uint4) -> fp32 FMA into two float4 accumulators
__device__ __forceinline__ void fma8(float4& a0, float4& a1, float dv, uint4 v) {
    float2 p0 = __half22float2(*reinterpret_cast<__half2*>(&v.x));
    float2 p1 = __half22float2(*reinterpret_cast<__half2*>(&v.y));
    float2 p2 = __half22float2(*reinterpret_cast<__half2*>(&v.z));
    float2 p3 = __half22float2(*reinterpret_cast<__half2*>(&v.w));
    a0.x += dv * p0.x; a0.y += dv * p0.y; a0.z += dv * p1.x; a0.w += dv * p1.y;
    a1.x += dv * p2.x; a1.y += dv * p2.y; a1.z += dv * p3.x; a1.w += dv * p3.y;
}
__device__ __forceinline__ void add8(float4& a0, float4& a1, uint4 v) {
    float2 p0 = __half22float2(*reinterpret_cast<__half2*>(&v.x));
    float2 p1 = __half22float2(*reinterpret_cast<__half2*>(&v.y));
    float2 p2 = __half22float2(*reinterpret_cast<__half2*>(&v.z));
    float2 p3 = __half22float2(*reinterpret_cast<__half2*>(&v.w));
    a0.x += p0.x; a0.y += p0.y; a0.z += p1.x; a0.w += p1.y;
    a1.x += p2.x; a1.y += p2.y; a1.z += p3.x; a1.w += p3.y;
}

// ------ t = (w*deg_e/256) ⊙ H^T @ (deg_v ⊙ out0)  (16B gather, 2 groups) -----
#define CAP_E 512
__global__ void __launch_bounds__(128) k_edge_gather_t() {
    int e    = blockIdx.x;
    int tid  = threadIdx.x;
    int feat = tid & 63;     // uint4 lane within row (64 x 16B = 1KB)
    int grp  = tid >> 6;     // 0/1: alternating nonzeros
    __shared__ int   idx[CAP_E];
    __shared__ float dvs[CAP_E];
    __shared__ float red[64 * 8];
    __shared__ int   cnt;
    if (tid == 0) cnt = 0;
    __syncthreads();
    for (int j = tid; j < WN; j += 128) {
        uint32_t w = g_HTB[(size_t)e * WN + j];
        if (w) {
            int pos = atomicAdd(&cnt, __popc(w));
            while (w) {
                int k = __ffs(w) - 1; w &= w - 1;
                if (pos < CAP_E) idx[pos] = j * 32 + k;
                pos++;
            }
        }
    }
    __syncthreads();
    int m = cnt < CAP_E ? cnt : CAP_E;
    for (int i = tid; i < m; i += 128) dvs[i] = g_degv[idx[i]];
    __syncthreads();

    const uint4* z4 = reinterpret_cast<const uint4*>(g_zh);  // 64 uint4 per row
    float4 a0 = {0.f, 0.f, 0.f, 0.f}, a1 = {0.f, 0.f, 0.f, 0.f};
    int i = grp;
    for (; i + 6 < m; i += 8) {
        uint4 v0 = z4[(size_t)idx[i]     * 64 + feat];
        uint4 v1 = z4[(size_t)idx[i + 2] * 64 + feat];
        uint4 v2 = z4[(size_t)idx[i + 4] * 64 + feat];
        uint4 v3 = z4[(size_t)idx[i + 6] * 64 + feat];
        fma8(a0, a1, dvs[i],     v0);
        fma8(a0, a1, dvs[i + 2], v1);
        fma8(a0, a1, dvs[i + 4], v2);
        fma8(a0, a1, dvs[i + 6], v3);
    }
    for (; i < m; i += 2)
        fma8(a0, a1, dvs[i], z4[(size_t)idx[i] * 64 + feat]);

    if (grp == 1) {
        *reinterpret_cast<float4*>(&red[feat * 8])     = a0;
        *reinterpret_cast<float4*>(&red[feat * 8 + 4]) = a1;
    }
    __syncthreads();
    if (grp == 0) {
        float4 b0 = *reinterpret_cast<float4*>(&red[feat * 8]);
        float4 b1 = *reinterpret_cast<float4*>(&red[feat * 8 + 4]);
        float s = g_hw[e] * g_dege[e] * (1.f / 256.f);
        __half2 r[4];
        r[0] = __floats2half2_rn(s * (a0.x + b0.x), s * (a0.y + b0.y));
        r[1] = __floats2half2_rn(s * (a0.z + b0.z), s * (a0.w + b0.w));
        r[2] = __floats2half2_rn(s * (a1.x + b1.x), s * (a1.y + b1.y));
        r[3] = __floats2half2_rn(s * (a1.z + b1.z), s * (a1.w + b1.w));
        reinterpret_cast<uint4*>(g_th)[(size_t)e * 64 + feat] =
            *reinterpret_cast<uint4*>(r);
    }
}

// ------------ out = deg_v*256 ⊙ (H @ t) + bias  (16B gather, 2 groups) -------
#define CAP_V 320
__global__ void __launch_bounds__(128) k_vertex_gather(const float* __restrict__ bias,
                                                       float* __restrict__ out) {
    int n    = blockIdx.x;
    int tid  = threadIdx.x;
    int feat = tid & 63;
    int grp  = tid >> 6;
    __shared__ int   idx[CAP_V];
    __shared__ float red[64 * 8];
    __shared__ int   cnt;
    if (tid == 0) cnt = 0;
    __syncthreads();
    if (tid < WE) {
        uint32_t w = g_HB[(size_t)n * WE + tid];
        if (w) {
            int pos = atomicAdd(&cnt, __popc(w));
            while (w) {
                int k = __ffs(w) - 1; w &= w - 1;
                if (pos < CAP_V) idx[pos] = tid * 32 + k;
                pos++;
            }
        }
    }
    __syncthreads();
    int m = cnt < CAP_V ? cnt : CAP_V;

    const uint4* t4 = reinterpret_cast<const uint4*>(g_th);
    float4 a0 = {0.f, 0.f, 0.f, 0.f}, a1 = {0.f, 0.f, 0.f, 0.f};
    int i = grp;
    for (; i + 6 < m; i += 8) {
        uint4 v0 = t4[(size_t)idx[i]     * 64 + feat];
        uint4 v1 = t4[(size_t)idx[i + 2] * 64 + feat];
        uint4 v2 = t4[(size_t)idx[i + 4] * 64 + feat];
        uint4 v3 = t4[(size_t)idx[i + 6] * 64 + feat];
        add8(a0, a1, v0); add8(a0, a1, v1);
        add8(a0, a1, v2); add8(a0, a1, v3);
    }
    for (; i < m; i += 2)
        add8(a0, a1, t4[(size_t)idx[i] * 64 + feat]);

    if (grp == 1) {
        *reinterpret_cast<float4*>(&red[feat * 8])     = a0;
        *reinterpret_cast<float4*>(&red[feat * 8 + 4]) = a1;
    }
    __syncthreads();
    if (grp == 0) {
        float4 b0 = *reinterpret_cast<float4*>(&red[feat * 8]);
        float4 b1 = *reinterpret_cast<float4*>(&red[feat * 8 + 4]);
        float dv = g_degv[n] * 256.f;                 // undo 2^-8 scale
        const float4* bias4 = reinterpret_cast<const float4*>(bias);
        float4 c0 = bias4[feat * 2], c1 = bias4[feat * 2 + 1];
        float4 r0 = {dv * (a0.x + b0.x) + c0.x, dv * (a0.y + b0.y) + c0.y,
                     dv * (a0.z + b0.z) + c0.z, dv * (a0.w + b0.w) + c0.w};
        float4 r1 = {dv * (a1.x + b1.x) + c1.x, dv * (a1.y + b1.y) + c1.y,
                     dv * (a1.z + b1.z) + c1.z, dv * (a1.w + b1.w) + c1.w};
        float4* o4 = reinterpret_cast<float4*>(out + (size_t)n * FT);
        o4[feat * 2]     = r0;
        o4[feat * 2 + 1] = r1;
    }
}

// ---------------- launch -----------------------------------------------------
extern "C" void kernel_launch(void* const* d_in, const int* in_sizes, int n_in,
                              void* d_out, int out_size) {
    const float* x      = (const float*)d_in[0];
    const float* H      = (const float*)d_in[1];
    const float* weight = (const float*)d_in[2];
    const float* V      = (const float*)d_in[3];
    const float* bias   = (const float*)d_in[4];
    float* out   = (float*)d_out;
    float* w_out = (float*)d_out + (size_t)N_V * FT;

    static cudaStream_t s2 = nullptr;
    static cudaEvent_t  evF = nullptr, evY = nullptr, evJ = nullptr;
    if (s2 == nullptr) {
        cudaStreamCreateWithFlags(&s2, cudaStreamNonBlocking);
        cudaEventCreateWithFlags(&evF, cudaEventDisableTiming);
        cudaEventCreateWithFlags(&evY, cudaEventDisableTiming);
        cudaEventCreateWithFlags(&evJ, cudaEventDisableTiming);
    }

    // Fork: xv + GEMM chain on side stream (independent of bitmask build).
    cudaEventRecord(evF, 0);
    cudaStreamWaitEvent(s2, evF, 0);
    k_xv       <<<N_V / 8, 256, 0, s2>>>(x, V);
    cudaEventRecord(evY, s2);
    k_splitA   <<<((size_t)N_V * FT / 8) / 256, 256, 0, s2>>>(x);
    k_splitB   <<<(FT * FT / 8) / 256, 256, 0, s2>>>(weight);
    k_gemm_wmma<<<dim3(FT / BN, N_V / BM), 256, 0, s2>>>();
    cudaEventRecord(evJ, s2);

    // Main stream: bitmask chain.
    k_build_bits<<<dim3(N_E / 256, N_V / 32), 256>>>(H);
    cudaStreamWaitEvent(0, evY, 0);     // hw needs y = xV
    k_hw_dege   <<<N_E / 4, 128>>>(w_out);
    k_degv      <<<N_V / 4, 128>>>();

    // Join, then the two dependent gathers.
    cudaStreamWaitEvent(0, evJ, 0);
    k_edge_gather_t<<<N_E, 128>>>();
    k_vertex_gather<<<N_V, 128>>>(bias, out);
}